// round 1
// baseline (speedup 1.0000x reference)
#include <cuda_runtime.h>
#include <math.h>

// Problem constants (fixed by setup_inputs)
#define EDIM 512
#define BDIM 4
#define SEQ  2048
#define NH   8
#define DH   64
#define ROWS (BDIM * SEQ)          // 8192

#define MAXNORM (1.0f - 4e-3f)     // geoopt projx eps for fp32, c=1

// ---------------- scratch (device globals: allocation-free) ----------------
__device__ float g_q[ROWS * EDIM];
__device__ float g_k[ROWS * EDIM];
__device__ float g_v[ROWS * EDIM];
__device__ float g_ao[ROWS * EDIM];
__device__ float g_qn[BDIM * NH * SEQ];
__device__ float g_kn[BDIM * NH * SEQ];

// ---------------- GEMM: C[M,N] = A[M,K] @ B[N,K]^T (NT), fp32 ----------------
// 64x64 tile, BK=16, 256 threads, 4x4 microtile.
#define GBK 16
__global__ __launch_bounds__(256) void gemm_nt(const float* __restrict__ A,
                                               const float* __restrict__ B,
                                               float* __restrict__ C,
                                               int M, int N, int K) {
    __shared__ float As[GBK][68];
    __shared__ float Bs[GBK][68];
    const int tid = threadIdx.x;
    const int tx = tid & 15, ty = tid >> 4;
    const int bm = blockIdx.y * 64, bn = blockIdx.x * 64;
    const int lr = tid >> 2;          // 0..63 (tile row to load)
    const int lc = (tid & 3) << 2;    // 0,4,8,12 (k-offset, float4)

    const float* Ap = A + (long)(bm + lr) * K + lc;
    const float* Bp = B + (long)(bn + lr) * K + lc;

    float acc[4][4] = {};

    for (int kt = 0; kt < K; kt += GBK) {
        float4 a4 = *(const float4*)(Ap + kt);
        float4 b4 = *(const float4*)(Bp + kt);
        As[lc + 0][lr] = a4.x; As[lc + 1][lr] = a4.y;
        As[lc + 2][lr] = a4.z; As[lc + 3][lr] = a4.w;
        Bs[lc + 0][lr] = b4.x; Bs[lc + 1][lr] = b4.y;
        Bs[lc + 2][lr] = b4.z; Bs[lc + 3][lr] = b4.w;
        __syncthreads();
#pragma unroll
        for (int k = 0; k < GBK; ++k) {
            float4 av = *(const float4*)&As[k][ty << 2];
            float4 bv = *(const float4*)&Bs[k][tx << 2];
            float a[4] = {av.x, av.y, av.z, av.w};
            float b[4] = {bv.x, bv.y, bv.z, bv.w};
#pragma unroll
            for (int i = 0; i < 4; ++i)
#pragma unroll
                for (int j = 0; j < 4; ++j)
                    acc[i][j] += a[i] * b[j];
        }
        __syncthreads();
    }
#pragma unroll
    for (int i = 0; i < 4; ++i) {
        float4 o = make_float4(acc[i][0], acc[i][1], acc[i][2], acc[i][3]);
        *(float4*)&C[(long)(bm + ty * 4 + i) * N + bn + tx * 4] = o;
    }
}

// ---------------- row-wise Mobius transform ----------------
// out = project(mobius_add(project(mobius_matvec_tail(x, mx)), bias))
// One block (128 threads) per row of 512 floats; each thread owns one float4.
__device__ __forceinline__ float blockReduce(float v, float* red) {
    const int t = threadIdx.x;
    __syncthreads();            // protect red from previous use
    red[t] = v;
    __syncthreads();
#pragma unroll
    for (int s = 64; s > 0; s >>= 1) {
        if (t < s) red[t] += red[t + s];
        __syncthreads();
    }
    return red[0];
}

__device__ __forceinline__ float dot4(float4 a, float4 b) {
    return a.x * b.x + a.y * b.y + a.z * b.z + a.w * b.w;
}

__global__ __launch_bounds__(128) void mobius_rows(const float* __restrict__ x,
                                                   const float* __restrict__ mx,
                                                   const float* __restrict__ bias,
                                                   float* __restrict__ out,
                                                   float* __restrict__ hn,
                                                   int with_hn) {
    __shared__ float red[128];
    __shared__ float hs[NH];
    const int t = threadIdx.x;
    const long r = blockIdx.x;

    const float4 xv = ((const float4*)(x + r * EDIM))[t];
    const float4 mv = ((const float4*)(mx + r * EDIM))[t];
    const float4 bv = ((const float4*)bias)[t];

    float x2 = blockReduce(dot4(xv, xv), red);
    float m2 = blockReduce(dot4(mv, mv), red);

    float xn = fmaxf(sqrtf(x2), 1e-15f);
    float mn = fmaxf(sqrtf(m2), 1e-15f);
    float u  = fminf(xn, 1.0f - 1e-7f);                 // artanh clip (xn>=0)
    float at = 0.5f * (log1pf(u) - log1pf(-u));
    float tt = tanhf(mn / xn * at);
    float sc = tt / mn;                                 // res = sc * mx (mx==0 -> res==0)

    float4 res = make_float4(mv.x * sc, mv.y * sc, mv.z * sc, mv.w * sc);
    float rn = fmaxf(tt, 1e-15f);
    float pf = (rn > MAXNORM) ? (MAXNORM / rn) : 1.0f;  // project
    res.x *= pf; res.y *= pf; res.z *= pf; res.w *= pf;

    // mobius_add(res, bias)
    float x2r = blockReduce(dot4(res, res), red);
    float y2  = blockReduce(dot4(bv, bv), red);
    float xy  = blockReduce(dot4(res, bv), red);
    float ca  = 1.0f + 2.0f * xy + y2;
    float cb  = 1.0f - x2r;
    float den = fmaxf(1.0f + 2.0f * xy + x2r * y2, 1e-15f);
    float inv = 1.0f / den;
    float4 o = make_float4((ca * res.x + cb * bv.x) * inv,
                           (ca * res.y + cb * bv.y) * inv,
                           (ca * res.z + cb * bv.z) * inv,
                           (ca * res.w + cb * bv.w) * inv);
    // project
    float o2 = blockReduce(dot4(o, o), red);
    float on = fmaxf(sqrtf(o2), 1e-15f);
    float pf2 = (on > MAXNORM) ? (MAXNORM / on) : 1.0f;
    o.x *= pf2; o.y *= pf2; o.z *= pf2; o.w *= pf2;

    ((float4*)(out + r * EDIM))[t] = o;

    if (with_hn) {
        if (t < NH) hs[t] = 0.0f;
        __syncthreads();
        atomicAdd(&hs[t >> 4], dot4(o, o));   // 16 threads (64 elems) per head
        __syncthreads();
        if (t < NH) {
            int b = (int)(r / SEQ), s = (int)(r % SEQ);
            hn[((long)b * NH + t) * SEQ + s] = fminf(hs[t], 1.0f - 1e-5f);
        }
    }
}

// ---------------- flash-style hyperbolic attention ----------------
// Block: 64 queries x full key stream, 256 threads (16x16), 4x4 microtiles.
// Smem (dynamic): Qst[d][r] 64x68, KPt (K transposed / P transposed, reused),
// Vs[c][d] 64x68, + qn/kn tiles.
#define SPITCH 68
#define ASMEM_FLOATS (3 * 64 * SPITCH + 128)
#define ASMEM_BYTES  (ASMEM_FLOATS * 4)

__global__ __launch_bounds__(256) void attn_kernel(const float* __restrict__ q,
                                                   const float* __restrict__ k,
                                                   const float* __restrict__ v,
                                                   const float* __restrict__ qn,
                                                   const float* __restrict__ kn,
                                                   float* __restrict__ o) {
    extern __shared__ float sm[];
    float* Qst = sm;                      // [DH][68]  Qst[d*68 + r]
    float* KPt = sm + 64 * SPITCH;        // dual: Kst[d][c] then Pt[c][r]
    float* Vs  = sm + 2 * 64 * SPITCH;    // [KT][68]  Vs[c*68 + d]
    float* qns = sm + 3 * 64 * SPITCH;    // 64
    float* kns = qns + 64;                // 64

    const int tid = threadIdx.x;
    const int tx = tid & 15, ty = tid >> 4;
    const int bh = blockIdx.y;            // 0..B*H-1
    const int b = bh >> 3, h = bh & 7;
    const int q0 = blockIdx.x * 64;

    const float* qbase = q + ((long)b * SEQ + q0) * EDIM + h * DH;

    // load Q tile transposed
#pragma unroll
    for (int it = 0; it < 4; ++it) {
        int slot = tid + it * 256;          // 0..1023 float4 slots
        int rr = slot >> 4;                 // 0..63
        int d4 = (slot & 15) << 2;          // 0..60
        float4 t4 = *(const float4*)(qbase + (long)rr * EDIM + d4);
        Qst[(d4 + 0) * SPITCH + rr] = t4.x;
        Qst[(d4 + 1) * SPITCH + rr] = t4.y;
        Qst[(d4 + 2) * SPITCH + rr] = t4.z;
        Qst[(d4 + 3) * SPITCH + rr] = t4.w;
    }
    if (tid < 64) qns[tid] = qn[((long)b * NH + h) * SEQ + q0 + tid];

    float m[4], l[4], O[4][4];
#pragma unroll
    for (int i = 0; i < 4; ++i) {
        m[i] = -1e30f; l[i] = 0.0f;
#pragma unroll
        for (int j = 0; j < 4; ++j) O[i][j] = 0.0f;
    }

    for (int kt = 0; kt < SEQ; kt += 64) {
        __syncthreads();   // prior-iter readers done (also covers Q-load visibility)
        const float* kbase = k + ((long)b * SEQ + kt) * EDIM + h * DH;
        const float* vbase = v + ((long)b * SEQ + kt) * EDIM + h * DH;
#pragma unroll
        for (int it = 0; it < 4; ++it) {
            int slot = tid + it * 256;
            int rr = slot >> 4;
            int d4 = (slot & 15) << 2;
            float4 t4 = *(const float4*)(kbase + (long)rr * EDIM + d4);
            KPt[(d4 + 0) * SPITCH + rr] = t4.x;
            KPt[(d4 + 1) * SPITCH + rr] = t4.y;
            KPt[(d4 + 2) * SPITCH + rr] = t4.z;
            KPt[(d4 + 3) * SPITCH + rr] = t4.w;
            float4 v4 = *(const float4*)(vbase + (long)rr * EDIM + d4);
            *(float4*)&Vs[rr * SPITCH + d4] = v4;
        }
        if (tid < 64) kns[tid] = kn[((long)b * NH + h) * SEQ + kt + tid];
        __syncthreads();

        // S = Q K^T (4x4 per thread)
        float acc[4][4] = {};
#pragma unroll
        for (int d = 0; d < DH; ++d) {
            float4 qv = *(const float4*)&Qst[d * SPITCH + (ty << 2)];
            float4 kv = *(const float4*)&KPt[d * SPITCH + (tx << 2)];
            float a[4] = {qv.x, qv.y, qv.z, qv.w};
            float bb[4] = {kv.x, kv.y, kv.z, kv.w};
#pragma unroll
            for (int i = 0; i < 4; ++i)
#pragma unroll
                for (int j = 0; j < 4; ++j)
                    acc[i][j] += a[i] * bb[j];
        }

        // hyperbolic score + online softmax
        float p[4][4];
#pragma unroll
        for (int i = 0; i < 4; ++i) {
            float qnv = qns[ty * 4 + i];
            float oq = 1.0f - qnv;
            float sc[4];
#pragma unroll
            for (int j = 0; j < 4; ++j) {
                float knv = kns[tx * 4 + j];
                float den = oq * (1.0f - knv) + 1e-5f;
                float delta = 2.0f * (acc[i][j] - qnv * knv) / den;
                sc[j] = -sqrtf(fmaxf(delta, 1e-5f)) * 0.125f;  // / sqrt(Dh)
            }
            float mx = fmaxf(fmaxf(sc[0], sc[1]), fmaxf(sc[2], sc[3]));
#pragma unroll
            for (int off = 8; off >= 1; off >>= 1)
                mx = fmaxf(mx, __shfl_xor_sync(0xffffffffu, mx, off, 16));
            float mn_ = fmaxf(m[i], mx);
            float alpha = __expf(m[i] - mn_);
            float ps = 0.0f;
#pragma unroll
            for (int j = 0; j < 4; ++j) {
                p[i][j] = __expf(sc[j] - mn_);
                ps += p[i][j];
            }
#pragma unroll
            for (int off = 8; off >= 1; off >>= 1)
                ps += __shfl_xor_sync(0xffffffffu, ps, off, 16);
            l[i] = l[i] * alpha + ps;
            m[i] = mn_;
#pragma unroll
            for (int j = 0; j < 4; ++j) O[i][j] *= alpha;
        }

        __syncthreads();   // everyone done reading Kst before P overwrite
#pragma unroll
        for (int i = 0; i < 4; ++i)
#pragma unroll
            for (int j = 0; j < 4; ++j)
                KPt[(tx * 4 + j) * SPITCH + ty * 4 + i] = p[i][j];
        __syncthreads();

        // O += P V
#pragma unroll
        for (int c = 0; c < 64; ++c) {
            float4 pv = *(const float4*)&KPt[c * SPITCH + (ty << 2)];
            float4 vv = *(const float4*)&Vs[c * SPITCH + (tx << 2)];
            float a[4] = {pv.x, pv.y, pv.z, pv.w};
            float bb[4] = {vv.x, vv.y, vv.z, vv.w};
#pragma unroll
            for (int i = 0; i < 4; ++i)
#pragma unroll
                for (int j = 0; j < 4; ++j)
                    O[i][j] += a[i] * bb[j];
        }
    }

    float* obase = o + ((long)b * SEQ + q0) * EDIM + h * DH;
#pragma unroll
    for (int i = 0; i < 4; ++i) {
        float invl = 1.0f / l[i];
        float4 ov = make_float4(O[i][0] * invl, O[i][1] * invl,
                                O[i][2] * invl, O[i][3] * invl);
        *(float4*)(obase + (long)(ty * 4 + i) * EDIM + tx * 4) = ov;
    }
}

// ---------------- launch ----------------
extern "C" void kernel_launch(void* const* d_in, const int* in_sizes, int n_in,
                              void* d_out, int out_size) {
    const float* x  = (const float*)d_in[0];
    const float* Wq = (const float*)d_in[1];
    const float* bq = (const float*)d_in[2];
    const float* Wk = (const float*)d_in[3];
    const float* bk = (const float*)d_in[4];
    const float* Wv = (const float*)d_in[5];
    const float* bv = (const float*)d_in[6];
    const float* Wo = (const float*)d_in[7];
    const float* bo = (const float*)d_in[8];
    float* out = (float*)d_out;

    float *q, *k, *v, *ao, *qn, *kn;
    cudaGetSymbolAddress((void**)&q,  g_q);
    cudaGetSymbolAddress((void**)&k,  g_k);
    cudaGetSymbolAddress((void**)&v,  g_v);
    cudaGetSymbolAddress((void**)&ao, g_ao);
    cudaGetSymbolAddress((void**)&qn, g_qn);
    cudaGetSymbolAddress((void**)&kn, g_kn);

    cudaFuncSetAttribute(attn_kernel, cudaFuncAttributeMaxDynamicSharedMemorySize,
                         ASMEM_BYTES);

    dim3 gg(EDIM / 64, ROWS / 64);          // (8, 128)
    gemm_nt<<<gg, 256>>>(x, Wq, q, ROWS, EDIM, EDIM);
    gemm_nt<<<gg, 256>>>(x, Wk, k, ROWS, EDIM, EDIM);
    gemm_nt<<<gg, 256>>>(x, Wv, v, ROWS, EDIM, EDIM);

    mobius_rows<<<ROWS, 128>>>(x, q, bq, q, qn, 1);
    mobius_rows<<<ROWS, 128>>>(x, k, bk, k, kn, 1);
    mobius_rows<<<ROWS, 128>>>(x, v, bv, v, nullptr, 0);

    dim3 ag(SEQ / 64, BDIM * NH);           // (32, 32)
    attn_kernel<<<ag, 256, ASMEM_BYTES>>>(q, k, v, qn, kn, ao);

    gemm_nt<<<gg, 256>>>(ao, Wo, q, ROWS, EDIM, EDIM);
    mobius_rows<<<ROWS, 128>>>(ao, q, bo, out, nullptr, 0);
}